// round 14
// baseline (speedup 1.0000x reference)
#include <cuda_runtime.h>
#include <cuda_fp16.h>
#include <math.h>
#include <stdint.h>

// Problem constants
#define Bb 4
#define Ll 4096
#define Hh 1024
#define Nn 16
#define Pc 32           // elements per scan thread
#define EPSV 1e-6f

// ---------------- scratch (static device globals; no allocation) ----------------
__device__ float  g_u  [(size_t)Bb*Hh*Ll];   // normalized, masked, (B,H,L)  64MB
__device__ float2 g_lam  [Hh*Nn];
__device__ float2 g_cd2  [Hh*Nn];
__device__ float2 g_lamPk[6 * Hh * Nn];      // lamP^(2^k), k=0..5   (lamP = lam^32)
__device__ float2 g_lamPw[Hh * 32 * Nn];     // lamP^(lane+1)        4MB
__device__ __half g_wf16[2048u*1024u];            // W fp16 [o][k]      4MB
__device__ __half g_yf16[(size_t)1024u*16384u];   // Y fp16 [k=h][n]   32MB

// ================= PTX helpers (legal on base compute_103) =================
__device__ __forceinline__ uint32_t smem_u32(const void* p) {
    uint32_t a;
    asm("{ .reg .u64 t; cvta.to.shared.u64 t, %1; cvt.u32.u64 %0, t; }" : "=r"(a) : "l"(p));
    return a;
}
__device__ __forceinline__ void cp16(uint32_t dst, const void* src) {
    asm volatile("cp.async.cg.shared.global [%0], [%1], 16;" :: "r"(dst), "l"(src));
}
__device__ __forceinline__ void cp_commit() { asm volatile("cp.async.commit_group;"); }
__device__ __forceinline__ void cp_wait2()  { asm volatile("cp.async.wait_group 2;"); }
__device__ __forceinline__ void ldsm4(uint32_t* r, uint32_t addr) {
    asm volatile("ldmatrix.sync.aligned.m8n8.x4.shared.b16 {%0,%1,%2,%3}, [%4];"
                 : "=r"(r[0]), "=r"(r[1]), "=r"(r[2]), "=r"(r[3]) : "r"(addr));
}
__device__ __forceinline__ void ldsm4t(uint32_t* r, uint32_t addr) {
    asm volatile("ldmatrix.sync.aligned.m8n8.x4.trans.shared.b16 {%0,%1,%2,%3}, [%4];"
                 : "=r"(r[0]), "=r"(r[1]), "=r"(r[2]), "=r"(r[3]) : "r"(addr));
}
__device__ __forceinline__ void mma16816(float* d, const uint32_t* a, const uint32_t* b) {
    asm volatile("mma.sync.aligned.m16n8k16.row.col.f32.f16.f16.f32 "
                 "{%0,%1,%2,%3}, {%4,%5,%6,%7}, {%8,%9}, {%0,%1,%2,%3};"
                 : "+f"(d[0]), "+f"(d[1]), "+f"(d[2]), "+f"(d[3])
                 : "r"(a[0]), "r"(a[1]), "r"(a[2]), "r"(a[3]), "r"(b[0]), "r"(b[1]));
}

// ---------------- kernel 0: constants + power tables (iterative cmul) + W->fp16 ----
__global__ void fused_pre_kernel(const float* __restrict__ log_dt,
                                 const float* __restrict__ log_A_real,
                                 const float* __restrict__ A_imag,
                                 const float* __restrict__ C_real,
                                 const float* __restrict__ C_imag,
                                 const float* __restrict__ wmat) {
    unsigned int bid = blockIdx.x;
    if (bid < 8192u) {
        unsigned int i = bid * 256 + threadIdx.x;
        g_wf16[i] = __float2half_rn(wmat[i]);
        return;
    }
    int idx = (int)(bid - 8192u) * 256 + threadIdx.x;
    if (idx >= Hh * Nn) return;
    int h = idx / Nn;
    int n = idx - h * Nn;
    double dt  = exp((double)log_dt[h]);
    double Are = -exp((double)log_A_real[idx]);
    double Aim = (double)A_imag[idx];
    double dre = Are * dt, dim = Aim * dt;
    double er  = exp(dre);
    double lr  = er * cos(dim), li = er * sin(dim);
    g_lam[idx] = make_float2((float)lr, (float)li);
    double magP = dre * (double)Pc, angP = dim * (double)Pc;
    double erp = exp(magP);
    double pr = erp * cos(angP), pi = erp * sin(angP);
    {
        double qr = pr, qi = pi;
#pragma unroll
        for (int k = 0; k < 6; k++) {
            g_lamPk[k * (Hh * Nn) + idx] = make_float2((float)qr, (float)qi);
            double t = qr * qr - qi * qi;
            qi = 2.0 * qr * qi;
            qr = t;
        }
    }
    {
        double qr = pr, qi = pi;
        for (int j = 0; j < 32; j++) {
            g_lamPw[((size_t)h * 32 + j) * Nn + n] = make_float2((float)qr, (float)qi);
            double t = qr * pr - qi * pi;
            qi = qr * pi + qi * pr;
            qr = t;
        }
    }
    double e1r = lr - 1.0, e1i = li;
    double Cr = (double)C_real[idx], Ci = (double)C_imag[idx];
    double nr = Cr * e1r - Ci * e1i;
    double ni = Cr * e1i + Ci * e1r;
    double den = Are * Are + Aim * Aim;
    double cdr = (nr * Are + ni * Aim) / den;
    double cdi = (ni * Are - nr * Aim) / den;
    g_cd2[idx] = make_float2((float)(2.0 * cdr), (float)(2.0 * cdi));
}

// ---------------- kernel 1: fused RMSNorm + mask + transpose ----------------
#define NF_TILE  (32 * 1025)
#define NF_SMEM  ((NF_TILE + 32 + 1024) * 4)
__global__ __launch_bounds__(256) void norm_fused_kernel(const float* __restrict__ hs,
                                                         const float* __restrict__ mask,
                                                         const float* __restrict__ w) {
    extern __shared__ float sm[];
    float* tile = sm;
    float* rm   = sm + NF_TILE;
    float* w_s  = sm + NF_TILE + 32;
    int b  = blockIdx.y;
    int l0 = blockIdx.x * 32;
    int tid = threadIdx.x;
    int row = tid >> 3;
    int sub = tid & 7;

    for (int i = tid; i < 1024; i += 256) w_s[i] = w[i];

    const float4* src = (const float4*)(hs + ((size_t)(b * Ll + l0 + row)) * Hh);
    float ss = 0.f;
#pragma unroll
    for (int i = 0; i < 32; i++) {
        int col4 = i * 8 + sub;
        float4 v = src[col4];
        ss += v.x * v.x + v.y * v.y + v.z * v.z + v.w * v.w;
        float* dst = &tile[row * 1025 + col4 * 4];
        dst[0] = v.x; dst[1] = v.y; dst[2] = v.z; dst[3] = v.w;
    }
#pragma unroll
    for (int o = 4; o; o >>= 1) ss += __shfl_xor_sync(0xffffffffu, ss, o);
    if (sub == 0)
        rm[row] = rsqrtf(ss * (1.0f / Hh) + EPSV) * mask[b * Ll + l0 + row];
    __syncthreads();

#pragma unroll 8
    for (int i = 0; i < 128; i++) {
        int lin = i * 256 + tid;
        int h = lin >> 5, l = lin & 31;
        g_u[((size_t)(b * Hh + h)) * Ll + l0 + l] = tile[l * 1025 + h] * rm[l] * w_s[h];
    }
}

// ---------------- kernel 2: FUSED scan, scalar math, u cached in registers ---------
__global__ __launch_bounds__(128) void scan_fused_kernel(const float* __restrict__ Dvec) {
    int bh  = blockIdx.x;
    int hh  = bh & (Hh - 1);
    int b   = bh >> 10;
    int tid = threadIdx.x;
    int lane = tid & 31, wrp = tid >> 5;

    // single global read of this thread's 32 u values
    float u[Pc];
    {
        const float4* up = (const float4*)(g_u + (size_t)bh * Ll + tid * Pc);
#pragma unroll
        for (int q = 0; q < Pc / 4; q++) {
            float4 v = up[q];
            u[q * 4] = v.x; u[q * 4 + 1] = v.y; u[q * 4 + 2] = v.z; u[q * 4 + 3] = v.w;
        }
    }

    float lr[Nn], li[Nn], sr[Nn], si[Nn];
#pragma unroll
    for (int n = 0; n < Nn; n++) {
        float2 v = g_lam[hh * Nn + n];
        lr[n] = v.x; li[n] = v.y; sr[n] = 0.f; si[n] = 0.f;
    }

    // ---- phase 1: local scan of 32 cached elements ----
#pragma unroll
    for (int e = 0; e < Pc; e++) {
        float x = u[e];
#pragma unroll
        for (int n = 0; n < Nn; n++) {
            float nr = fmaf(lr[n], sr[n], fmaf(-li[n], si[n], x));
            float ni = fmaf(lr[n], si[n], li[n] * sr[n]);
            sr[n] = nr; si[n] = ni;
        }
    }

    // ---- phase 2: Kogge-Stone over 32 lanes; step multipliers from table ----
#pragma unroll
    for (int k = 0; k < 5; k++) {
        int off = 1 << k;
        const float2* mk = g_lamPk + k * (Hh * Nn) + hh * Nn;
#pragma unroll
        for (int n = 0; n < Nn; n++) {
            float2 m = mk[n];
            float vr = __shfl_up_sync(0xffffffffu, sr[n], off);
            float vi = __shfl_up_sync(0xffffffffu, si[n], off);
            float nsr = fmaf(m.x, vr, fmaf(-m.y, vi, sr[n]));
            float nsi = fmaf(m.x, vi, fmaf(m.y, vr, si[n]));
            if (lane >= off) { sr[n] = nsr; si[n] = nsi; }
        }
    }

    // cross-warp combine with M32 = lamP^32
    __shared__ float2 Sw[4][Nn];
    if (lane == 31) {
#pragma unroll
        for (int n = 0; n < Nn; n++) Sw[wrp][n] = make_float2(sr[n], si[n]);
    }
    __syncthreads();
    {
        const float2* mk = g_lamPk + 5 * (Hh * Nn) + hh * Nn;
        const float2* pw = g_lamPw + ((size_t)hh * 32 + lane) * Nn;
#pragma unroll
        for (int n = 0; n < Nn; n++) {
            float2 m = mk[n];
            float Orr = 0.f, Oii = 0.f;
            for (int j = 0; j < wrp; j++) {
                float2 sj = Sw[j][n];
                float t = fmaf(m.x, Orr, fmaf(-m.y, Oii, sj.x));
                Oii     = fmaf(m.x, Oii, fmaf(m.y, Orr, sj.y));
                Orr     = t;
            }
            float2 p = pw[n];
            float ir = fmaf(p.x, Orr, fmaf(-p.y, Oii, sr[n]));
            float ii = fmaf(p.x, Oii, fmaf(p.y, Orr, si[n]));
            float tr = __shfl_up_sync(0xffffffffu, ir, 1);
            float ti = __shfl_up_sync(0xffffffffu, ii, 1);
            sr[n] = (lane == 0) ? Orr : tr;
            si[n] = (lane == 0) ? Oii : ti;
        }
    }

    // ---- phase 3: replay from cached u + output dot + D skip + exact GELU ----
    float cr[Nn], ci[Nn];
#pragma unroll
    for (int n = 0; n < Nn; n++) {
        float2 cc = g_cd2[hh * Nn + n];
        cr[n] = cc.x; ci[n] = cc.y;
    }
    float Dh = Dvec[hh];
    uint2* yp = (uint2*)(g_yf16 + (size_t)hh * 16384 + (size_t)b * 4096 + tid * Pc);
#pragma unroll
    for (int q = 0; q < Pc / 4; q++) {
        float ys[4];
#pragma unroll
        for (int e = 0; e < 4; e++) {
            float x = u[q * 4 + e];
            float y = Dh * x;
#pragma unroll
            for (int n = 0; n < Nn; n++) {
                float nr = fmaf(lr[n], sr[n], fmaf(-li[n], si[n], x));
                float ni = fmaf(lr[n], si[n], li[n] * sr[n]);
                sr[n] = nr; si[n] = ni;
                y = fmaf(cr[n], nr, y);
                y = fmaf(-ci[n], ni, y);
            }
            ys[e] = 0.5f * y * (1.0f + erff(y * 0.70710678118654752f));
        }
        __half2 h2a = __floats2half2_rn(ys[0], ys[1]);
        __half2 h2b = __floats2half2_rn(ys[2], ys[3]);
        uint2 pk;
        pk.x = *(uint32_t*)&h2a;
        pk.y = *(uint32_t*)&h2b;
        yp[q] = pk;
    }
}

// ---------------- kernel 3: fp16 1-pass GEMM + GLU + residual (R7-proven loop) -----
#define KC 32
#define ROWA 80
#define ROWB2 528
#define A_REG (128*ROWA)
#define B_REG (KC*ROWB2)
#define STG (A_REG + B_REG)
#define NSTG 4
#define GSMEM (NSTG*STG)

__device__ __forceinline__ void load_stage(uint32_t sbase, int s, int chunk, int by, int bx) {
    int tid = threadIdx.x;
    uint32_t stb = sbase + s * STG;
    {
        int row = tid >> 2, seg = tid & 3;
        int wrow = (row < 64) ? (by * 64 + row) : (1024 + by * 64 + row - 64);
        cp16(stb + (unsigned)row * ROWA + seg * 16,
             g_wf16 + (size_t)wrow * 1024 + chunk * KC + seg * 8);
    }
#pragma unroll
    for (int i = 0; i < 2; i++) {
        int t = i * 512 + tid;
        int row = t >> 5, seg = t & 31;
        cp16(stb + A_REG + (unsigned)row * ROWB2 + seg * 16,
             g_yf16 + (size_t)(chunk * KC + row) * 16384 + bx * 256 + seg * 8);
    }
}

__global__ __launch_bounds__(512, 1) void gemm_glu_kernel(const float* __restrict__ bias,
                                                          const float* __restrict__ hs,
                                                          float* __restrict__ out) {
    extern __shared__ char smem[];
    uint32_t sbase = smem_u32(smem);
    int tid  = threadIdx.x;
    int wid  = tid >> 5;
    int lane = tid & 31;
    int by = blockIdx.x;
    int bx = blockIdx.y;

    int wm = (wid & 1) * 64;
    int wn = (wid >> 1) * 32;
    uint32_t aOff = (uint32_t)(wm + (lane & 15)) * ROWA + (uint32_t)(lane >> 4) * 16;
    uint32_t bOff = (uint32_t)(lane & 15) * ROWB2 + (uint32_t)(lane >> 4) * 16
                  + (uint32_t)wn * 2;

    float acc[64];
#pragma unroll
    for (int i = 0; i < 64; i++) acc[i] = 0.f;

#pragma unroll
    for (int p = 0; p < 3; p++) { load_stage(sbase, p, p, by, bx); cp_commit(); }

    for (int c = 0; c < 32; c++) {
        int s = c & 3;
        cp_wait2();
        __syncthreads();
        if (c + 3 < 32) load_stage(sbase, (c + 3) & 3, c + 3, by, bx);
        cp_commit();
        uint32_t ab = sbase + s * STG;
        uint32_t bb = ab + A_REG;
#pragma unroll
        for (int ks = 0; ks < 2; ks++) {
            uint32_t bf[8], af[16];
            ldsm4t(&bf[0], bb + bOff + (unsigned)ks * (16 * ROWB2));
            ldsm4t(&bf[4], bb + bOff + (unsigned)ks * (16 * ROWB2) + 32);
#pragma unroll
            for (int i = 0; i < 4; i++)
                ldsm4(&af[i * 4], ab + aOff + (unsigned)i * (16 * ROWA) + ks * 32);
#pragma unroll
            for (int i = 0; i < 4; i++)
#pragma unroll
                for (int j = 0; j < 4; j++)
                    mma16816(&acc[(i * 4 + j) * 4], &af[i * 4], &bf[j * 2]);
        }
    }

    float* zsm = (float*)smem;
    int qr = lane >> 2, t4 = lane & 3;
    int n0 = bx * 256, o0 = by * 64;
#pragma unroll
    for (int r = 0; r < 2; r++) {
        __syncthreads();
        if ((wn >> 7) == r) {
            int wnl = wn & 127;
#pragma unroll
            for (int i = 0; i < 4; i++)
#pragma unroll
                for (int j = 0; j < 4; j++) {
                    int m = wm + i * 16 + qr;
                    int n = wnl + j * 8 + t4 * 2;
                    const float* p = &acc[(i * 4 + j) * 4];
                    zsm[n * 132 + m]           = p[0];
                    zsm[(n + 1) * 132 + m]     = p[1];
                    zsm[n * 132 + m + 8]       = p[2];
                    zsm[(n + 1) * 132 + m + 8] = p[3];
                }
        }
        __syncthreads();
#pragma unroll
        for (int it = 0; it < 4; it++) {
            int task = it * 512 + tid;
            int nrow = task >> 4, mg = (task & 15) * 4;
            float4 za = *(const float4*)&zsm[nrow * 132 + mg];
            float4 zg = *(const float4*)&zsm[nrow * 132 + 64 + mg];
            float4 ba = *(const float4*)(bias + o0 + mg);
            float4 bg = *(const float4*)(bias + 1024 + o0 + mg);
            size_t addr = (size_t)(n0 + r * 128 + nrow) * 1024 + o0 + mg;
            float4 hv = *(const float4*)(hs + addr);
            float4 ov;
            ov.x = hv.x + (za.x + ba.x) * (1.0f / (1.0f + expf(-(zg.x + bg.x))));
            ov.y = hv.y + (za.y + ba.y) * (1.0f / (1.0f + expf(-(zg.y + bg.y))));
            ov.z = hv.z + (za.z + ba.z) * (1.0f / (1.0f + expf(-(zg.z + bg.z))));
            ov.w = hv.w + (za.w + ba.w) * (1.0f / (1.0f + expf(-(zg.w + bg.w))));
            *(float4*)(out + addr) = ov;
        }
    }
}

// ---------------- launch ----------------
extern "C" void kernel_launch(void* const* d_in, const int* in_sizes, int n_in,
                              void* d_out, int out_size) {
    const float* hidden     = (const float*)d_in[0];
    const float* attn_mask  = (const float*)d_in[1];
    const float* norm_w     = (const float*)d_in[2];
    const float* log_dt     = (const float*)d_in[3];
    const float* log_A_real = (const float*)d_in[4];
    const float* A_imag     = (const float*)d_in[5];
    const float* C_real     = (const float*)d_in[6];
    const float* C_imag     = (const float*)d_in[7];
    const float* Dvec       = (const float*)d_in[8];
    const float* out_w      = (const float*)d_in[9];
    const float* out_b      = (const float*)d_in[10];
    float* out = (float*)d_out;

    cudaFuncSetAttribute(gemm_glu_kernel, cudaFuncAttributeMaxDynamicSharedMemorySize, GSMEM);
    cudaFuncSetAttribute(norm_fused_kernel, cudaFuncAttributeMaxDynamicSharedMemorySize, NF_SMEM);

    fused_pre_kernel<<<8192 + 64, 256>>>(log_dt, log_A_real, A_imag, C_real, C_imag, out_w);
    norm_fused_kernel<<<dim3(Ll / 32, Bb), 256, NF_SMEM>>>(hidden, attn_mask, norm_w);
    scan_fused_kernel<<<Bb * Hh, 128>>>(Dvec);
    gemm_glu_kernel<<<dim3(16, 64), 512, GSMEM>>>(out_b, hidden, out);
}

// round 16
// speedup vs baseline: 1.1277x; 1.1277x over previous
#include <cuda_runtime.h>
#include <cuda_fp16.h>
#include <math.h>
#include <stdint.h>

// Problem constants
#define Bb 4
#define Ll 4096
#define Hh 1024
#define Nn 16
#define CH 64            // chunk length
#define NCOL 256         // columns per h = Bb * (Ll/CH)
#define EPSV 1e-6f

// ---------------- scratch (static device globals; no allocation) ----------------
__device__ float  g_u   [(size_t)Bb*Hh*Ll];        // normalized, masked, (B,H,L) 64MB
__device__ __half g_wf16[2048u*1024u];             // W fp16 [o][k]       4MB
__device__ __half g_yf16[(size_t)1024u*16384u];    // Y fp16 [k=h][n]    32MB
__device__ __half g_Afull[(size_t)Hh*128*64];      // per-h conv A [128][64] 16MB
__device__ __half g_Av  [(size_t)Hh*64*64];        // per-h boundary A [64][64] 8MB
__device__ float2 g_lam64[Hh*Nn];                  // lam^64
__device__ float  g_yc  [(size_t)Hh*NCOL*CH];      // conv partial y [h][c][t] 64MB
__device__ float2 g_Sloc[(size_t)Hh*NCOL*Nn];      // chunk-local end states 32MB
__device__ float2 g_Sin [(size_t)Hh*NCOL*Nn];      // chunk input states 32MB

// ================= PTX helpers (legal on base compute_103) =================
__device__ __forceinline__ uint32_t smem_u32(const void* p) {
    uint32_t a;
    asm("{ .reg .u64 t; cvta.to.shared.u64 t, %1; cvt.u32.u64 %0, t; }" : "=r"(a) : "l"(p));
    return a;
}
__device__ __forceinline__ void cp16(uint32_t dst, const void* src) {
    asm volatile("cp.async.cg.shared.global [%0], [%1], 16;" :: "r"(dst), "l"(src));
}
__device__ __forceinline__ void cp_commit() { asm volatile("cp.async.commit_group;"); }
__device__ __forceinline__ void cp_wait2()  { asm volatile("cp.async.wait_group 2;"); }
__device__ __forceinline__ void ldsm4(uint32_t* r, uint32_t addr) {
    asm volatile("ldmatrix.sync.aligned.m8n8.x4.shared.b16 {%0,%1,%2,%3}, [%4];"
                 : "=r"(r[0]), "=r"(r[1]), "=r"(r[2]), "=r"(r[3]) : "r"(addr));
}
__device__ __forceinline__ void ldsm4t(uint32_t* r, uint32_t addr) {
    asm volatile("ldmatrix.sync.aligned.m8n8.x4.trans.shared.b16 {%0,%1,%2,%3}, [%4];"
                 : "=r"(r[0]), "=r"(r[1]), "=r"(r[2]), "=r"(r[3]) : "r"(addr));
}
__device__ __forceinline__ void mma16816(float* d, const uint32_t* a, const uint32_t* b) {
    asm volatile("mma.sync.aligned.m16n8k16.row.col.f32.f16.f16.f32 "
                 "{%0,%1,%2,%3}, {%4,%5,%6,%7}, {%8,%9}, {%0,%1,%2,%3};"
                 : "+f"(d[0]), "+f"(d[1]), "+f"(d[2]), "+f"(d[3])
                 : "r"(a[0]), "r"(a[1]), "r"(a[2]), "r"(a[3]), "r"(b[0]), "r"(b[1]));
}

// ---------------- kernel 0: W fp32 -> fp16 ----------------
__global__ void wconv_kernel(const float* __restrict__ wmat) {
    unsigned int i = blockIdx.x * 256u + threadIdx.x;
    g_wf16[i] = __float2half_rn(wmat[i]);
}

// ---------------- kernel 0b: per-h operator matrices (double precision) -----------
__global__ __launch_bounds__(128) void prep2_kernel(const float* __restrict__ log_dt,
                                                    const float* __restrict__ log_A_real,
                                                    const float* __restrict__ A_imag,
                                                    const float* __restrict__ C_real,
                                                    const float* __restrict__ C_imag,
                                                    const float* __restrict__ Dvec) {
    __shared__ float2 lamPow[CH + 1][Nn];
    __shared__ float2 cds[Nn];
    __shared__ float  kd[CH];
    int h = blockIdx.x;
    int tid = threadIdx.x;

    if (tid < Nn) {
        int idx = h * Nn + tid;
        double dt  = exp((double)log_dt[h]);
        double Are = -exp((double)log_A_real[idx]);
        double Aim = (double)A_imag[idx];
        double dre = Are * dt, dim = Aim * dt;
        double er  = exp(dre);
        double lr  = er * cos(dim), li = er * sin(dim);
        double e1r = lr - 1.0, e1i = li;
        double Cr = (double)C_real[idx], Ci = (double)C_imag[idx];
        double nr = Cr * e1r - Ci * e1i;
        double ni = Cr * e1i + Ci * e1r;
        double den = Are * Are + Aim * Aim;
        cds[tid] = make_float2((float)(2.0 * (nr * Are + ni * Aim) / den),
                               (float)(2.0 * (ni * Are - nr * Aim) / den));
        double qr = 1.0, qi = 0.0;
        for (int d = 0; d <= CH; d++) {
            lamPow[d][tid] = make_float2((float)qr, (float)qi);
            double t = qr * lr - qi * li;
            qi = qr * li + qi * lr;
            qr = t;
        }
        g_lam64[h * Nn + tid] = lamPow[CH][tid];
    }
    __syncthreads();
    if (tid < CH) {
        float s = 0.f;
#pragma unroll
        for (int n = 0; n < Nn; n++) {
            float2 lp = lamPow[tid][n];
            float2 cd = cds[n];
            s += cd.x * lp.x - cd.y * lp.y;
        }
        if (tid == 0) s += Dvec[h];
        kd[tid] = s;
    }
    __syncthreads();
    // A_full [128 rows][64 cols]: rows 0..63 Toeplitz T, 64..127 E (Re_hi,Im_hi,Re_lo,Im_lo)
#pragma unroll 8
    for (int it = 0; it < 64; it++) {
        int idx = it * 128 + tid;
        int row = idx >> 6, j = idx & 63;
        __half v;
        if (row < CH) {
            int d = row - j;
            v = (d >= 0) ? __float2half_rn(kd[d]) : __float2half_rn(0.f);
        } else {
            int n = (row - CH) & 15;
            int grp = (row - CH) >> 4;
            float2 lp = lamPow[63 - j][n];
            float val = (grp & 1) ? lp.y : lp.x;
            if (grp >= 2) {
                float hi = __half2float(__float2half_rn(val));
                v = __float2half_rn(val - hi);
            } else {
                v = __float2half_rn(val);
            }
        }
        g_Afull[(size_t)h * 8192 + idx] = v;
    }
    // A_v [64 t][64 cols]: cols 0-15 Vr, 16-31 -Vi, 32-47 Vr, 48-63 -Vi ; V = cd2*lam^(t+1)
#pragma unroll 8
    for (int it = 0; it < 32; it++) {
        int idx = it * 128 + tid;
        int t = idx >> 6, col = idx & 63;
        int n = col & 15, grp = (col >> 4) & 1;
        float2 lp = lamPow[t + 1][n];
        float2 cd = cds[n];
        float Vr = cd.x * lp.x - cd.y * lp.y;
        float Vi = cd.x * lp.y + cd.y * lp.x;
        g_Av[(size_t)h * 4096 + idx] = __float2half_rn(grp ? -Vi : Vr);
    }
}

// ---------------- kernel 1: fused RMSNorm + mask + transpose ----------------
#define NF_TILE  (32 * 1025)
#define NF_SMEM  ((NF_TILE + 32 + 1024) * 4)
__global__ __launch_bounds__(256) void norm_fused_kernel(const float* __restrict__ hs,
                                                         const float* __restrict__ mask,
                                                         const float* __restrict__ w) {
    extern __shared__ float sm[];
    float* tile = sm;
    float* rm   = sm + NF_TILE;
    float* w_s  = sm + NF_TILE + 32;
    int b  = blockIdx.y;
    int l0 = blockIdx.x * 32;
    int tid = threadIdx.x;
    int row = tid >> 3;
    int sub = tid & 7;

    for (int i = tid; i < 1024; i += 256) w_s[i] = w[i];

    const float4* src = (const float4*)(hs + ((size_t)(b * Ll + l0 + row)) * Hh);
    float ss = 0.f;
#pragma unroll
    for (int i = 0; i < 32; i++) {
        int col4 = i * 8 + sub;
        float4 v = src[col4];
        ss += v.x * v.x + v.y * v.y + v.z * v.z + v.w * v.w;
        float* dst = &tile[row * 1025 + col4 * 4];
        dst[0] = v.x; dst[1] = v.y; dst[2] = v.z; dst[3] = v.w;
    }
#pragma unroll
    for (int o = 4; o; o >>= 1) ss += __shfl_xor_sync(0xffffffffu, ss, o);
    if (sub == 0)
        rm[row] = rsqrtf(ss * (1.0f / Hh) + EPSV) * mask[b * Ll + l0 + row];
    __syncthreads();

#pragma unroll 8
    for (int i = 0; i < 128; i++) {
        int lin = i * 256 + tid;
        int h = lin >> 5, l = lin & 31;
        g_u[((size_t)(b * Hh + h)) * Ll + l0 + l] = tile[l * 1025 + h] * rm[l] * w_s[h];
    }
}

// ---------------- kernel 2: conv GEMM per h: [128x64] @ [64x256] ----------------
#define CAROW 144
#define CONV_ASZ (128 * CAROW)    // 18432
#define CONV_BSZ (256 * CAROW)    // 36864
#define CONV_SMEM 67584

__global__ __launch_bounds__(512, 1) void conv_kernel() {
    extern __shared__ char smem[];
    int h = blockIdx.x;
    int tid  = threadIdx.x;
    int wid  = tid >> 5;
    int lane = tid & 31;

    // load A_full (16KB): 128 rows x 8 uint4
    {
        const uint4* Ag = (const uint4*)(g_Afull + (size_t)h * 8192);
#pragma unroll
        for (int it = 0; it < 2; it++) {
            int t = it * 512 + tid;
            int row = t >> 3, seg = t & 7;
            *(uint4*)(smem + row * CAROW + seg * 16) = Ag[t];
        }
    }
    // load + convert u -> B smem [c=256 rows][j=64 cols] fp16
    {
#pragma unroll
        for (int it = 0; it < 8; it++) {
            int i4 = it * 512 + tid;
            int b = i4 >> 10;
            int l = (i4 & 1023) * 4;
            int chunk = l >> 6, j = l & 63;
            int c = (b << 6) | chunk;
            float4 v = *(const float4*)(g_u + ((size_t)(b * Hh + h)) * Ll + l);
            __half2 h0 = __floats2half2_rn(v.x, v.y);
            __half2 h1 = __floats2half2_rn(v.z, v.w);
            uint2 pk;
            pk.x = *(uint32_t*)&h0;
            pk.y = *(uint32_t*)&h1;
            *(uint2*)(smem + CONV_ASZ + c * CAROW + j * 2) = pk;
        }
    }
    __syncthreads();

    uint32_t sbase = smem_u32(smem);
    uint32_t ab = sbase, bb = sbase + CONV_ASZ;
    int wm = (wid & 1) * 64;
    int wn = (wid >> 1) * 32;
    uint32_t aOff = (uint32_t)(wm + (lane & 15)) * CAROW + (uint32_t)(lane >> 4) * 16;
    uint32_t bOff = (uint32_t)(wn + (lane & 15)) * CAROW + (uint32_t)(lane >> 4) * 16;

    float acc[64];
#pragma unroll
    for (int i = 0; i < 64; i++) acc[i] = 0.f;

#pragma unroll
    for (int ks = 0; ks < 4; ks++) {
        uint32_t koff = ks * 32;
        uint32_t br[8], af[16];
        ldsm4(&br[0], bb + bOff + koff);
        ldsm4(&br[4], bb + bOff + 16 * CAROW + koff);
#pragma unroll
        for (int i = 0; i < 4; i++)
            ldsm4(&af[i * 4], ab + aOff + (unsigned)i * (16 * CAROW) + koff);
        uint32_t bp[4][2] = {{br[0], br[2]}, {br[1], br[3]}, {br[4], br[6]}, {br[5], br[7]}};
#pragma unroll
        for (int i = 0; i < 4; i++)
#pragma unroll
            for (int j = 0; j < 4; j++)
                mma16816(&acc[(i * 4 + j) * 4], &af[i * 4], bp[j]);
    }
    __syncthreads();

    float* zsm = (float*)smem;                // [128 n][132 m]
    int qr = lane >> 2, t4 = lane & 3;
#pragma unroll
    for (int r = 0; r < 2; r++) {
        __syncthreads();
        if ((wn >> 7) == r) {
            int wnl = wn & 127;
#pragma unroll
            for (int i = 0; i < 4; i++)
#pragma unroll
                for (int j = 0; j < 4; j++) {
                    int m = wm + i * 16 + qr;
                    int n = wnl + j * 8 + t4 * 2;
                    const float* p = &acc[(i * 4 + j) * 4];
                    zsm[n * 132 + m]           = p[0];
                    zsm[(n + 1) * 132 + m]     = p[1];
                    zsm[n * 132 + m + 8]       = p[2];
                    zsm[(n + 1) * 132 + m + 8] = p[3];
                }
        }
        __syncthreads();
#pragma unroll
        for (int it = 0; it < 4; it++) {
            int task = it * 512 + tid;
            int c_loc = task >> 4, quad = task & 15;
            float4 v = *(const float4*)&zsm[c_loc * 132 + quad * 4];
            *(float4*)(g_yc + ((size_t)h * NCOL + r * 128 + c_loc) * CH + quad * 4) = v;
        }
#pragma unroll
        for (int it = 0; it < 4; it++) {
            int task = it * 512 + tid;
            int c_loc = task >> 4, n = task & 15;
            int base = c_loc * 132;
            float Sr = zsm[base + 64 + n] + zsm[base + 96 + n];
            float Si = zsm[base + 80 + n] + zsm[base + 112 + n];
            g_Sloc[((size_t)h * NCOL + r * 128 + c_loc) * Nn + n] = make_float2(Sr, Si);
        }
    }
}

// ---------------- kernel 3: inter-chunk state recurrence ----------------
__global__ void combine_kernel() {
    int gt = blockIdx.x * 256 + threadIdx.x;
    int n = gt & 15;
    int h = (gt >> 4) & 1023;
    int b = gt >> 14;
    float2 l64 = g_lam64[h * Nn + n];
    float sr = 0.f, si = 0.f;
#pragma unroll
    for (int chunk = 0; chunk < CH; chunk++) {
        size_t idx = ((size_t)h * NCOL + (b * 64 + chunk)) * Nn + n;
        g_Sin[idx] = make_float2(sr, si);
        float2 sl = g_Sloc[idx];
        float nr = fmaf(l64.x, sr, fmaf(-l64.y, si, sl.x));
        float ni = fmaf(l64.x, si, fmaf(l64.y, sr, sl.y));
        sr = nr; si = ni;
    }
}

// ---------------- kernel 4: boundary GEMM + add y_conv + exact GELU -> yf16 -------
#define BND_ASZ (64 * 144)        // 9216
#define BND_BROW 528
#define BND_BSZ (64 * BND_BROW)   // 33792
#define BND_SMEM 69632            // zsm [256][68] fp32

__global__ __launch_bounds__(256, 1) void boundary_kernel() {
    extern __shared__ char smem[];
    int h = blockIdx.x;
    int tid  = threadIdx.x;
    int wid  = tid >> 5;
    int lane = tid & 31;

    // load A_v (8KB): 64 rows x 8 uint4  (FIXED indexing)
    {
        const uint4* Ag = (const uint4*)(g_Av + (size_t)h * 4096);
#pragma unroll
        for (int it = 0; it < 2; it++) {
            int t = it * 256 + tid;
            int row = t >> 3, seg = t & 7;
            *(uint4*)(smem + row * 144 + seg * 16) = Ag[t];
        }
    }
    // build B: rows 0-15 sr_hi, 16-31 si_hi, 32-47 sr_lo, 48-63 si_lo ; cols = c
    {
        int c = tid;
        const float2* sp = (const float2*)g_Sin + ((size_t)h * NCOL + c) * Nn;
        char* Bsm = smem + BND_ASZ;
#pragma unroll
        for (int n = 0; n < Nn; n++) {
            float2 s = sp[n];
            __half rh = __float2half_rn(s.x);
            __half rl = __float2half_rn(s.x - __half2float(rh));
            __half ih = __float2half_rn(s.y);
            __half il = __float2half_rn(s.y - __half2float(ih));
            *(__half*)(Bsm + (n)      * BND_BROW + c * 2) = rh;
            *(__half*)(Bsm + (16 + n) * BND_BROW + c * 2) = ih;
            *(__half*)(Bsm + (32 + n) * BND_BROW + c * 2) = rl;
            *(__half*)(Bsm + (48 + n) * BND_BROW + c * 2) = il;
        }
    }
    __syncthreads();

    uint32_t sbase = smem_u32(smem);
    uint32_t ab = sbase, bb = sbase + BND_ASZ;
    int wn = wid * 32;                                 // FIXED: 8 warps cover 256 cols
    uint32_t aOff = (uint32_t)(lane & 15) * 144 + (uint32_t)(lane >> 4) * 16;
    uint32_t bOff = (uint32_t)(lane & 15) * BND_BROW + (uint32_t)(lane >> 4) * 16
                  + (uint32_t)wn * 2;

    float acc[64];
#pragma unroll
    for (int i = 0; i < 64; i++) acc[i] = 0.f;

#pragma unroll
    for (int ks = 0; ks < 4; ks++) {
        uint32_t bf[8], af[16];
        ldsm4t(&bf[0], bb + bOff + (unsigned)ks * (16 * BND_BROW));
        ldsm4t(&bf[4], bb + bOff + (unsigned)ks * (16 * BND_BROW) + 32);
#pragma unroll
        for (int i = 0; i < 4; i++)
            ldsm4(&af[i * 4], ab + aOff + (unsigned)i * (16 * 144) + ks * 32);
#pragma unroll
        for (int i = 0; i < 4; i++)
#pragma unroll
            for (int j = 0; j < 4; j++)
                mma16816(&acc[(i * 4 + j) * 4], &af[i * 4], &bf[j * 2]);
    }
    __syncthreads();

    float* zsm = (float*)smem;     // [256 c][68 t]
    int qr = lane >> 2, t4 = lane & 3;
#pragma unroll
    for (int i = 0; i < 4; i++)
#pragma unroll
        for (int j = 0; j < 4; j++) {
            int m = i * 16 + qr;
            int n = wn + j * 8 + t4 * 2;
            const float* p = &acc[(i * 4 + j) * 4];
            zsm[n * 68 + m]           = p[0];
            zsm[(n + 1) * 68 + m]     = p[1];
            zsm[n * 68 + m + 8]       = p[2];
            zsm[(n + 1) * 68 + m + 8] = p[3];
        }
    __syncthreads();

    // final: y = y_conv + bnd ; exact GELU ; write fp16 [h][b*4096 + chunk*64 + t]
#pragma unroll
    for (int it = 0; it < 16; it++) {
        int task = it * 256 + tid;
        int c = task >> 4, q = task & 15;
        int t0 = q * 4;
        float4 yv = *(const float4*)(g_yc + ((size_t)h * NCOL + c) * CH + t0);
        float y0 = yv.x + zsm[c * 68 + t0];
        float y1 = yv.y + zsm[c * 68 + t0 + 1];
        float y2 = yv.z + zsm[c * 68 + t0 + 2];
        float y3 = yv.w + zsm[c * 68 + t0 + 3];
        y0 = 0.5f * y0 * (1.0f + erff(y0 * 0.70710678118654752f));
        y1 = 0.5f * y1 * (1.0f + erff(y1 * 0.70710678118654752f));
        y2 = 0.5f * y2 * (1.0f + erff(y2 * 0.70710678118654752f));
        y3 = 0.5f * y3 * (1.0f + erff(y3 * 0.70710678118654752f));
        __half2 p0 = __floats2half2_rn(y0, y1);
        __half2 p1 = __floats2half2_rn(y2, y3);
        uint2 pk;
        pk.x = *(uint32_t*)&p0;
        pk.y = *(uint32_t*)&p1;
        size_t off = (size_t)h * 16384 + (c >> 6) * 4096 + (c & 63) * 64 + t0;
        *(uint2*)(g_yf16 + off) = pk;
    }
}

// ---------------- kernel 5: fp16 1-pass GEMM + GLU + residual (proven) ----------
#define KC 32
#define ROWA 80
#define ROWB2 528
#define A_REG (128*ROWA)
#define B_REG (KC*ROWB2)
#define STG (A_REG + B_REG)
#define NSTG 4
#define GSMEM (NSTG*STG)

__device__ __forceinline__ void load_stage(uint32_t sbase, int s, int chunk, int by, int bx) {
    int tid = threadIdx.x;
    uint32_t stb = sbase + s * STG;
    {
        int row = tid >> 2, seg = tid & 3;
        int wrow = (row < 64) ? (by * 64 + row) : (1024 + by * 64 + row - 64);
        cp16(stb + (unsigned)row * ROWA + seg * 16,
             g_wf16 + (size_t)wrow * 1024 + chunk * KC + seg * 8);
    }
#pragma unroll
    for (int i = 0; i < 2; i++) {
        int t = i * 512 + tid;
        int row = t >> 5, seg = t & 31;
        cp16(stb + A_REG + (unsigned)row * ROWB2 + seg * 16,
             g_yf16 + (size_t)(chunk * KC + row) * 16384 + bx * 256 + seg * 8);
    }
}

__global__ __launch_bounds__(512, 1) void gemm_glu_kernel(const float* __restrict__ bias,
                                                          const float* __restrict__ hs,
                                                          float* __restrict__ out) {
    extern __shared__ char smem[];
    uint32_t sbase = smem_u32(smem);
    int tid  = threadIdx.x;
    int wid  = tid >> 5;
    int lane = tid & 31;
    int by = blockIdx.x;
    int bx = blockIdx.y;

    int wm = (wid & 1) * 64;
    int wn = (wid >> 1) * 32;
    uint32_t aOff = (uint32_t)(wm + (lane & 15)) * ROWA + (uint32_t)(lane >> 4) * 16;
    uint32_t bOff = (uint32_t)(lane & 15) * ROWB2 + (uint32_t)(lane >> 4) * 16
                  + (uint32_t)wn * 2;

    float acc[64];
#pragma unroll
    for (int i = 0; i < 64; i++) acc[i] = 0.f;

#pragma unroll
    for (int p = 0; p < 3; p++) { load_stage(sbase, p, p, by, bx); cp_commit(); }

    for (int c = 0; c < 32; c++) {
        int s = c & 3;
        cp_wait2();
        __syncthreads();
        if (c + 3 < 32) load_stage(sbase, (c + 3) & 3, c + 3, by, bx);
        cp_commit();
        uint32_t ab = sbase + s * STG;
        uint32_t bb = ab + A_REG;
#pragma unroll
        for (int ks = 0; ks < 2; ks++) {
            uint32_t bf[8], af[16];
            ldsm4t(&bf[0], bb + bOff + (unsigned)ks * (16 * ROWB2));
            ldsm4t(&bf[4], bb + bOff + (unsigned)ks * (16 * ROWB2) + 32);
#pragma unroll
            for (int i = 0; i < 4; i++)
                ldsm4(&af[i * 4], ab + aOff + (unsigned)i * (16 * ROWA) + ks * 32);
#pragma unroll
            for (int i = 0; i < 4; i++)
#pragma unroll
                for (int j = 0; j < 4; j++)
                    mma16816(&acc[(i * 4 + j) * 4], &af[i * 4], &bf[j * 2]);
        }
    }

    float* zsm = (float*)smem;
    int qr = lane >> 2, t4 = lane & 3;
    int n0 = bx * 256, o0 = by * 64;
#pragma unroll
    for (int r = 0; r < 2; r++) {
        __syncthreads();
        if ((wn >> 7) == r) {
            int wnl = wn & 127;
#pragma unroll
            for (int i = 0; i < 4; i++)
#pragma unroll
                for (int j = 0; j < 4; j++) {
                    int m = wm + i * 16 + qr;
                    int n = wnl + j * 8 + t4 * 2;
                    const float* p = &acc[(i * 4 + j) * 4];
                    zsm[n * 132 + m]           = p[0];
                    zsm[(n + 1) * 132 + m]     = p[1];
                    zsm[n * 132 + m + 8]       = p[2];
                    zsm[(n + 1) * 132 + m + 8] = p[3];
                }
        }
        __syncthreads();
#pragma unroll
        for (int it = 0; it < 4; it++) {
            int task = it * 512 + tid;
            int nrow = task >> 4, mg = (task & 15) * 4;
            float4 za = *(const float4*)&zsm[nrow * 132 + mg];
            float4 zg = *(const float4*)&zsm[nrow * 132 + 64 + mg];
            float4 ba = *(const float4*)(bias + o0 + mg);
            float4 bg = *(const float4*)(bias + 1024 + o0 + mg);
            size_t addr = (size_t)(n0 + r * 128 + nrow) * 1024 + o0 + mg;
            float4 hv = *(const float4*)(hs + addr);
            float4 ov;
            ov.x = hv.x + (za.x + ba.x) * (1.0f / (1.0f + expf(-(zg.x + bg.x))));
            ov.y = hv.y + (za.y + ba.y) * (1.0f / (1.0f + expf(-(zg.y + bg.y))));
            ov.z = hv.z + (za.z + ba.z) * (1.0f / (1.0f + expf(-(zg.z + bg.z))));
            ov.w = hv.w + (za.w + ba.w) * (1.0f / (1.0f + expf(-(zg.w + bg.w))));
            *(float4*)(out + addr) = ov;
        }
    }
}

// ---------------- launch ----------------
extern "C" void kernel_launch(void* const* d_in, const int* in_sizes, int n_in,
                              void* d_out, int out_size) {
    const float* hidden     = (const float*)d_in[0];
    const float* attn_mask  = (const float*)d_in[1];
    const float* norm_w     = (const float*)d_in[2];
    const float* log_dt     = (const float*)d_in[3];
    const float* log_A_real = (const float*)d_in[4];
    const float* A_imag     = (const float*)d_in[5];
    const float* C_real     = (const float*)d_in[6];
    const float* C_imag     = (const float*)d_in[7];
    const float* Dvec       = (const float*)d_in[8];
    const float* out_w      = (const float*)d_in[9];
    const float* out_b      = (const float*)d_in[10];
    float* out = (float*)d_out;

    cudaFuncSetAttribute(gemm_glu_kernel, cudaFuncAttributeMaxDynamicSharedMemorySize, GSMEM);
    cudaFuncSetAttribute(norm_fused_kernel, cudaFuncAttributeMaxDynamicSharedMemorySize, NF_SMEM);
    cudaFuncSetAttribute(conv_kernel, cudaFuncAttributeMaxDynamicSharedMemorySize, CONV_SMEM);
    cudaFuncSetAttribute(boundary_kernel, cudaFuncAttributeMaxDynamicSharedMemorySize, BND_SMEM);

    wconv_kernel<<<8192, 256>>>(out_w);
    prep2_kernel<<<Hh, 128>>>(log_dt, log_A_real, A_imag, C_real, C_imag, Dvec);
    norm_fused_kernel<<<dim3(Ll / 32, Bb), 256, NF_SMEM>>>(hidden, attn_mask, norm_w);
    conv_kernel<<<Hh, 512, CONV_SMEM>>>();
    combine_kernel<<<256, 256>>>();
    boundary_kernel<<<Hh, 256, BND_SMEM>>>();
    gemm_glu_kernel<<<dim3(16, 64), 512, GSMEM>>>(out_b, hidden, out);
}

// round 17
// speedup vs baseline: 1.1513x; 1.0209x over previous
#include <cuda_runtime.h>
#include <cuda_fp16.h>
#include <math.h>
#include <stdint.h>

// Problem constants
#define Bb 4
#define Ll 4096
#define Hh 1024
#define Nn 16
#define CH 64            // chunk length
#define NCOL 256         // columns per h = Bb * (Ll/CH)
#define EPSV 1e-6f

// ---------------- scratch (static device globals; no allocation) ----------------
__device__ float  g_u   [(size_t)Bb*Hh*Ll];        // normalized, masked, (B,H,L) 64MB
__device__ __half g_wf16[2048u*1024u];             // W fp16 [o][k]       4MB
__device__ __half g_yf16[(size_t)1024u*16384u];    // Y fp16 [k=h][n]    32MB
__device__ __half g_Afull[(size_t)Hh*128*64];      // per-h conv A [128][64] 16MB
__device__ __half g_Av  [(size_t)Hh*64*64];        // per-h boundary A [64][64] 8MB
__device__ float2 g_lam64[Hh*Nn];                  // lam^64
__device__ __half g_yc16[(size_t)Hh*NCOL*CH];      // conv partial y fp16 32MB
__device__ float2 g_Sloc[(size_t)Hh*NCOL*Nn];      // chunk-local end states 32MB

// ================= PTX helpers (legal on base compute_103) =================
__device__ __forceinline__ uint32_t smem_u32(const void* p) {
    uint32_t a;
    asm("{ .reg .u64 t; cvta.to.shared.u64 t, %1; cvt.u32.u64 %0, t; }" : "=r"(a) : "l"(p));
    return a;
}
__device__ __forceinline__ void cp16(uint32_t dst, const void* src) {
    asm volatile("cp.async.cg.shared.global [%0], [%1], 16;" :: "r"(dst), "l"(src));
}
__device__ __forceinline__ void cp_commit() { asm volatile("cp.async.commit_group;"); }
__device__ __forceinline__ void cp_wait2()  { asm volatile("cp.async.wait_group 2;"); }
__device__ __forceinline__ void ldsm4(uint32_t* r, uint32_t addr) {
    asm volatile("ldmatrix.sync.aligned.m8n8.x4.shared.b16 {%0,%1,%2,%3}, [%4];"
                 : "=r"(r[0]), "=r"(r[1]), "=r"(r[2]), "=r"(r[3]) : "r"(addr));
}
__device__ __forceinline__ void ldsm4t(uint32_t* r, uint32_t addr) {
    asm volatile("ldmatrix.sync.aligned.m8n8.x4.trans.shared.b16 {%0,%1,%2,%3}, [%4];"
                 : "=r"(r[0]), "=r"(r[1]), "=r"(r[2]), "=r"(r[3]) : "r"(addr));
}
__device__ __forceinline__ void mma16816(float* d, const uint32_t* a, const uint32_t* b) {
    asm volatile("mma.sync.aligned.m16n8k16.row.col.f32.f16.f16.f32 "
                 "{%0,%1,%2,%3}, {%4,%5,%6,%7}, {%8,%9}, {%0,%1,%2,%3};"
                 : "+f"(d[0]), "+f"(d[1]), "+f"(d[2]), "+f"(d[3])
                 : "r"(a[0]), "r"(a[1]), "r"(a[2]), "r"(a[3]), "r"(b[0]), "r"(b[1]));
}

// ---------------- kernel 0: W fp32 -> fp16 ----------------
__global__ void wconv_kernel(const float* __restrict__ wmat) {
    unsigned int i = blockIdx.x * 256u + threadIdx.x;
    g_wf16[i] = __float2half_rn(wmat[i]);
}

// ---------------- kernel 0b: per-h operator matrices (double precision) -----------
__global__ __launch_bounds__(128) void prep2_kernel(const float* __restrict__ log_dt,
                                                    const float* __restrict__ log_A_real,
                                                    const float* __restrict__ A_imag,
                                                    const float* __restrict__ C_real,
                                                    const float* __restrict__ C_imag,
                                                    const float* __restrict__ Dvec) {
    __shared__ float2 lamPow[CH + 1][Nn];
    __shared__ float2 cds[Nn];
    __shared__ float  kd[CH];
    int h = blockIdx.x;
    int tid = threadIdx.x;

    if (tid < Nn) {
        int idx = h * Nn + tid;
        double dt  = exp((double)log_dt[h]);
        double Are = -exp((double)log_A_real[idx]);
        double Aim = (double)A_imag[idx];
        double dre = Are * dt, dim = Aim * dt;
        double er  = exp(dre);
        double lr  = er * cos(dim), li = er * sin(dim);
        double e1r = lr - 1.0, e1i = li;
        double Cr = (double)C_real[idx], Ci = (double)C_imag[idx];
        double nr = Cr * e1r - Ci * e1i;
        double ni = Cr * e1i + Ci * e1r;
        double den = Are * Are + Aim * Aim;
        cds[tid] = make_float2((float)(2.0 * (nr * Are + ni * Aim) / den),
                               (float)(2.0 * (ni * Are - nr * Aim) / den));
        double qr = 1.0, qi = 0.0;
        for (int d = 0; d <= CH; d++) {
            lamPow[d][tid] = make_float2((float)qr, (float)qi);
            double t = qr * lr - qi * li;
            qi = qr * li + qi * lr;
            qr = t;
        }
        g_lam64[h * Nn + tid] = lamPow[CH][tid];
    }
    __syncthreads();
    if (tid < CH) {
        float s = 0.f;
#pragma unroll
        for (int n = 0; n < Nn; n++) {
            float2 lp = lamPow[tid][n];
            float2 cd = cds[n];
            s += cd.x * lp.x - cd.y * lp.y;
        }
        if (tid == 0) s += Dvec[h];
        kd[tid] = s;
    }
    __syncthreads();
#pragma unroll 8
    for (int it = 0; it < 64; it++) {
        int idx = it * 128 + tid;
        int row = idx >> 6, j = idx & 63;
        __half v;
        if (row < CH) {
            int d = row - j;
            v = (d >= 0) ? __float2half_rn(kd[d]) : __float2half_rn(0.f);
        } else {
            int n = (row - CH) & 15;
            int grp = (row - CH) >> 4;
            float2 lp = lamPow[63 - j][n];
            float val = (grp & 1) ? lp.y : lp.x;
            if (grp >= 2) {
                float hi = __half2float(__float2half_rn(val));
                v = __float2half_rn(val - hi);
            } else {
                v = __float2half_rn(val);
            }
        }
        g_Afull[(size_t)h * 8192 + idx] = v;
    }
#pragma unroll 8
    for (int it = 0; it < 32; it++) {
        int idx = it * 128 + tid;
        int t = idx >> 6, col = idx & 63;
        int n = col & 15, grp = (col >> 4) & 1;
        float2 lp = lamPow[t + 1][n];
        float2 cd = cds[n];
        float Vr = cd.x * lp.x - cd.y * lp.y;
        float Vi = cd.x * lp.y + cd.y * lp.x;
        g_Av[(size_t)h * 4096 + idx] = __float2half_rn(grp ? -Vi : Vr);
    }
}

// ---------------- kernel 1: fused RMSNorm + mask + transpose ----------------
#define NF_TILE  (32 * 1025)
#define NF_SMEM  ((NF_TILE + 32 + 1024) * 4)
__global__ __launch_bounds__(256) void norm_fused_kernel(const float* __restrict__ hs,
                                                         const float* __restrict__ mask,
                                                         const float* __restrict__ w) {
    extern __shared__ float sm[];
    float* tile = sm;
    float* rm   = sm + NF_TILE;
    float* w_s  = sm + NF_TILE + 32;
    int b  = blockIdx.y;
    int l0 = blockIdx.x * 32;
    int tid = threadIdx.x;
    int row = tid >> 3;
    int sub = tid & 7;

    for (int i = tid; i < 1024; i += 256) w_s[i] = w[i];

    const float4* src = (const float4*)(hs + ((size_t)(b * Ll + l0 + row)) * Hh);
    float ss = 0.f;
#pragma unroll
    for (int i = 0; i < 32; i++) {
        int col4 = i * 8 + sub;
        float4 v = src[col4];
        ss += v.x * v.x + v.y * v.y + v.z * v.z + v.w * v.w;
        float* dst = &tile[row * 1025 + col4 * 4];
        dst[0] = v.x; dst[1] = v.y; dst[2] = v.z; dst[3] = v.w;
    }
#pragma unroll
    for (int o = 4; o; o >>= 1) ss += __shfl_xor_sync(0xffffffffu, ss, o);
    if (sub == 0)
        rm[row] = rsqrtf(ss * (1.0f / Hh) + EPSV) * mask[b * Ll + l0 + row];
    __syncthreads();

#pragma unroll 8
    for (int i = 0; i < 128; i++) {
        int lin = i * 256 + tid;
        int h = lin >> 5, l = lin & 31;
        g_u[((size_t)(b * Hh + h)) * Ll + l0 + l] = tile[l * 1025 + h] * rm[l] * w_s[h];
    }
}

// ---------------- kernel 2: conv GEMM per h: [128x64] @ [64x256] ----------------
#define CAROW 144
#define CONV_ASZ (128 * CAROW)
#define CONV_SMEM 67584

__global__ __launch_bounds__(512, 1) void conv_kernel() {
    extern __shared__ char smem[];
    int h = blockIdx.x;
    int tid  = threadIdx.x;
    int wid  = tid >> 5;
    int lane = tid & 31;

    {
        const uint4* Ag = (const uint4*)(g_Afull + (size_t)h * 8192);
#pragma unroll
        for (int it = 0; it < 2; it++) {
            int t = it * 512 + tid;
            int row = t >> 3, seg = t & 7;
            *(uint4*)(smem + row * CAROW + seg * 16) = Ag[t];
        }
    }
    {
#pragma unroll
        for (int it = 0; it < 8; it++) {
            int i4 = it * 512 + tid;
            int b = i4 >> 10;
            int l = (i4 & 1023) * 4;
            int chunk = l >> 6, j = l & 63;
            int c = (b << 6) | chunk;
            float4 v = *(const float4*)(g_u + ((size_t)(b * Hh + h)) * Ll + l);
            __half2 h0 = __floats2half2_rn(v.x, v.y);
            __half2 h1 = __floats2half2_rn(v.z, v.w);
            uint2 pk;
            pk.x = *(uint32_t*)&h0;
            pk.y = *(uint32_t*)&h1;
            *(uint2*)(smem + CONV_ASZ + c * CAROW + j * 2) = pk;
        }
    }
    __syncthreads();

    uint32_t sbase = smem_u32(smem);
    uint32_t ab = sbase, bb = sbase + CONV_ASZ;
    int wm = (wid & 1) * 64;
    int wn = (wid >> 1) * 32;
    uint32_t aOff = (uint32_t)(wm + (lane & 15)) * CAROW + (uint32_t)(lane >> 4) * 16;
    uint32_t bOff = (uint32_t)(wn + (lane & 15)) * CAROW + (uint32_t)(lane >> 4) * 16;

    float acc[64];
#pragma unroll
    for (int i = 0; i < 64; i++) acc[i] = 0.f;

#pragma unroll
    for (int ks = 0; ks < 4; ks++) {
        uint32_t koff = ks * 32;
        uint32_t br[8], af[16];
        ldsm4(&br[0], bb + bOff + koff);
        ldsm4(&br[4], bb + bOff + 16 * CAROW + koff);
#pragma unroll
        for (int i = 0; i < 4; i++)
            ldsm4(&af[i * 4], ab + aOff + (unsigned)i * (16 * CAROW) + koff);
        uint32_t bp[4][2] = {{br[0], br[2]}, {br[1], br[3]}, {br[4], br[6]}, {br[5], br[7]}};
#pragma unroll
        for (int i = 0; i < 4; i++)
#pragma unroll
            for (int j = 0; j < 4; j++)
                mma16816(&acc[(i * 4 + j) * 4], &af[i * 4], bp[j]);
    }
    __syncthreads();

    float* zsm = (float*)smem;                // [128 n][132 m]
    int qr = lane >> 2, t4 = lane & 3;
#pragma unroll
    for (int r = 0; r < 2; r++) {
        __syncthreads();
        if ((wn >> 7) == r) {
            int wnl = wn & 127;
#pragma unroll
            for (int i = 0; i < 4; i++)
#pragma unroll
                for (int j = 0; j < 4; j++) {
                    int m = wm + i * 16 + qr;
                    int n = wnl + j * 8 + t4 * 2;
                    const float* p = &acc[(i * 4 + j) * 4];
                    zsm[n * 132 + m]           = p[0];
                    zsm[(n + 1) * 132 + m]     = p[1];
                    zsm[n * 132 + m + 8]       = p[2];
                    zsm[(n + 1) * 132 + m + 8] = p[3];
                }
        }
        __syncthreads();
        // y_conv (fp16 now)
#pragma unroll
        for (int it = 0; it < 4; it++) {
            int task = it * 512 + tid;
            int c_loc = task >> 4, quad = task & 15;
            const float* zp = &zsm[c_loc * 132 + quad * 4];
            __half2 p0 = __floats2half2_rn(zp[0], zp[1]);
            __half2 p1 = __floats2half2_rn(zp[2], zp[3]);
            uint2 pk;
            pk.x = *(uint32_t*)&p0;
            pk.y = *(uint32_t*)&p1;
            *(uint2*)(g_yc16 + ((size_t)h * NCOL + r * 128 + c_loc) * CH + quad * 4) = pk;
        }
#pragma unroll
        for (int it = 0; it < 4; it++) {
            int task = it * 512 + tid;
            int c_loc = task >> 4, n = task & 15;
            int base = c_loc * 132;
            float Sr = zsm[base + 64 + n] + zsm[base + 96 + n];
            float Si = zsm[base + 80 + n] + zsm[base + 112 + n];
            g_Sloc[((size_t)h * NCOL + r * 128 + c_loc) * Nn + n] = make_float2(Sr, Si);
        }
    }
}

// ---------------- kernel 3: boundary (combine fused) + y_conv + GELU -> yf16 -------
// smem: [A_v 9216][B 33792][Sloc padded 256*17*8 = 34816] = 77824 ; zsm reuse = 69632
#define BND_ASZ  9216
#define BND_BROW 528
#define BND_BOFF BND_ASZ
#define BND_SOFF (BND_ASZ + 33792)
#define BND_SMEM 77824

__global__ __launch_bounds__(256, 1) void boundary_kernel() {
    extern __shared__ char smem[];
    int h = blockIdx.x;
    int tid  = threadIdx.x;
    int wid  = tid >> 5;
    int lane = tid & 31;
    float2* S = (float2*)(smem + BND_SOFF);    // [c][n] stride 17 float2

    // load A_v (8KB): 64 rows x 8 uint4
    {
        const uint4* Ag = (const uint4*)(g_Av + (size_t)h * 4096);
#pragma unroll
        for (int it = 0; it < 2; it++) {
            int t = it * 256 + tid;
            int row = t >> 3, seg = t & 7;
            *(uint4*)(smem + row * 144 + seg * 16) = Ag[t];
        }
    }
    // load Sloc -> padded smem (coalesced float2)
    {
        const float2* Sg = g_Sloc + (size_t)h * NCOL * Nn;
#pragma unroll
        for (int it = 0; it < 16; it++) {
            int i = it * 256 + tid;          // 4096 float2
            int c = i >> 4, n = i & 15;
            S[c * 17 + n] = Sg[i];
        }
    }
    __syncthreads();
    // inter-chunk recurrence in-place: S[chunk] := state BEFORE chunk
    if (tid < 64) {
        int b = tid >> 4, n = tid & 15;
        float2 l64 = g_lam64[h * Nn + n];
        float sr = 0.f, si = 0.f;
#pragma unroll
        for (int chunk = 0; chunk < CH; chunk++) {
            int idx = (b * 64 + chunk) * 17 + n;
            float2 sl = S[idx];
            S[idx] = make_float2(sr, si);
            float nr = fmaf(l64.x, sr, fmaf(-l64.y, si, sl.x));
            float ni = fmaf(l64.x, si, fmaf(l64.y, sr, sl.y));
            sr = nr; si = ni;
        }
    }
    __syncthreads();
    // build B: rows 0-15 sr_hi, 16-31 si_hi, 32-47 sr_lo, 48-63 si_lo ; cols = c
    {
        int c = tid;
        char* Bsm = smem + BND_BOFF;
#pragma unroll
        for (int n = 0; n < Nn; n++) {
            float2 s = S[c * 17 + n];
            __half rh = __float2half_rn(s.x);
            __half rl = __float2half_rn(s.x - __half2float(rh));
            __half ih = __float2half_rn(s.y);
            __half il = __float2half_rn(s.y - __half2float(ih));
            *(__half*)(Bsm + (n)      * BND_BROW + c * 2) = rh;
            *(__half*)(Bsm + (16 + n) * BND_BROW + c * 2) = ih;
            *(__half*)(Bsm + (32 + n) * BND_BROW + c * 2) = rl;
            *(__half*)(Bsm + (48 + n) * BND_BROW + c * 2) = il;
        }
    }
    __syncthreads();

    uint32_t sbase = smem_u32(smem);
    uint32_t ab = sbase, bb = sbase + BND_BOFF;
    int wn = wid * 32;
    uint32_t aOff = (uint32_t)(lane & 15) * 144 + (uint32_t)(lane >> 4) * 16;
    uint32_t bOff = (uint32_t)(lane & 15) * BND_BROW + (uint32_t)(lane >> 4) * 16
                  + (uint32_t)wn * 2;

    float acc[64];
#pragma unroll
    for (int i = 0; i < 64; i++) acc[i] = 0.f;

#pragma unroll
    for (int ks = 0; ks < 4; ks++) {
        uint32_t bf[8], af[16];
        ldsm4t(&bf[0], bb + bOff + (unsigned)ks * (16 * BND_BROW));
        ldsm4t(&bf[4], bb + bOff + (unsigned)ks * (16 * BND_BROW) + 32);
#pragma unroll
        for (int i = 0; i < 4; i++)
            ldsm4(&af[i * 4], ab + aOff + (unsigned)i * (16 * 144) + ks * 32);
#pragma unroll
        for (int i = 0; i < 4; i++)
#pragma unroll
            for (int j = 0; j < 4; j++)
                mma16816(&acc[(i * 4 + j) * 4], &af[i * 4], &bf[j * 2]);
    }
    __syncthreads();

    float* zsm = (float*)smem;     // [256 c][68 t]
    int qr = lane >> 2, t4 = lane & 3;
#pragma unroll
    for (int i = 0; i < 4; i++)
#pragma unroll
        for (int j = 0; j < 4; j++) {
            int m = i * 16 + qr;
            int n = wn + j * 8 + t4 * 2;
            const float* p = &acc[(i * 4 + j) * 4];
            zsm[n * 68 + m]           = p[0];
            zsm[(n + 1) * 68 + m]     = p[1];
            zsm[n * 68 + m + 8]       = p[2];
            zsm[(n + 1) * 68 + m + 8] = p[3];
        }
    __syncthreads();

#pragma unroll
    for (int it = 0; it < 16; it++) {
        int task = it * 256 + tid;
        int c = task >> 4, q = task & 15;
        int t0 = q * 4;
        uint2 yv = *(const uint2*)(g_yc16 + ((size_t)h * NCOL + c) * CH + t0);
        __half2 ya = *(__half2*)&yv.x;
        __half2 yb = *(__half2*)&yv.y;
        float y0 = __low2float(ya)  + zsm[c * 68 + t0];
        float y1 = __high2float(ya) + zsm[c * 68 + t0 + 1];
        float y2 = __low2float(yb)  + zsm[c * 68 + t0 + 2];
        float y3 = __high2float(yb) + zsm[c * 68 + t0 + 3];
        y0 = 0.5f * y0 * (1.0f + erff(y0 * 0.70710678118654752f));
        y1 = 0.5f * y1 * (1.0f + erff(y1 * 0.70710678118654752f));
        y2 = 0.5f * y2 * (1.0f + erff(y2 * 0.70710678118654752f));
        y3 = 0.5f * y3 * (1.0f + erff(y3 * 0.70710678118654752f));
        __half2 p0 = __floats2half2_rn(y0, y1);
        __half2 p1 = __floats2half2_rn(y2, y3);
        uint2 pk;
        pk.x = *(uint32_t*)&p0;
        pk.y = *(uint32_t*)&p1;
        size_t off = (size_t)h * 16384 + (c >> 6) * 4096 + (c & 63) * 64 + t0;
        *(uint2*)(g_yf16 + off) = pk;
    }
}

// ---------------- kernel 4: fp16 1-pass GEMM + GLU + residual (proven) ----------
#define KC 32
#define ROWA 80
#define ROWB2 528
#define A_REG (128*ROWA)
#define B_REG (KC*ROWB2)
#define STG (A_REG + B_REG)
#define NSTG 4
#define GSMEM (NSTG*STG)

__device__ __forceinline__ void load_stage(uint32_t sbase, int s, int chunk, int by, int bx) {
    int tid = threadIdx.x;
    uint32_t stb = sbase + s * STG;
    {
        int row = tid >> 2, seg = tid & 3;
        int wrow = (row < 64) ? (by * 64 + row) : (1024 + by * 64 + row - 64);
        cp16(stb + (unsigned)row * ROWA + seg * 16,
             g_wf16 + (size_t)wrow * 1024 + chunk * KC + seg * 8);
    }
#pragma unroll
    for (int i = 0; i < 2; i++) {
        int t = i * 512 + tid;
        int row = t >> 5, seg = t & 31;
        cp16(stb + A_REG + (unsigned)row * ROWB2 + seg * 16,
             g_yf16 + (size_t)(chunk * KC + row) * 16384 + bx * 256 + seg * 8);
    }
}

__global__ __launch_bounds__(512, 1) void gemm_glu_kernel(const float* __restrict__ bias,
                                                          const float* __restrict__ hs,
                                                          float* __restrict__ out) {
    extern __shared__ char smem[];
    uint32_t sbase = smem_u32(smem);
    int tid  = threadIdx.x;
    int wid  = tid >> 5;
    int lane = tid & 31;
    int by = blockIdx.x;
    int bx = blockIdx.y;

    int wm = (wid & 1) * 64;
    int wn = (wid >> 1) * 32;
    uint32_t aOff = (uint32_t)(wm + (lane & 15)) * ROWA + (uint32_t)(lane >> 4) * 16;
    uint32_t bOff = (uint32_t)(lane & 15) * ROWB2 + (uint32_t)(lane >> 4) * 16
                  + (uint32_t)wn * 2;

    float acc[64];
#pragma unroll
    for (int i = 0; i < 64; i++) acc[i] = 0.f;

#pragma unroll
    for (int p = 0; p < 3; p++) { load_stage(sbase, p, p, by, bx); cp_commit(); }

    for (int c = 0; c < 32; c++) {
        int s = c & 3;
        cp_wait2();
        __syncthreads();
        if (c + 3 < 32) load_stage(sbase, (c + 3) & 3, c + 3, by, bx);
        cp_commit();
        uint32_t ab = sbase + s * STG;
        uint32_t bb = ab + A_REG;
#pragma unroll
        for (int ks = 0; ks < 2; ks++) {
            uint32_t bf[8], af[16];
            ldsm4t(&bf[0], bb + bOff + (unsigned)ks * (16 * ROWB2));
            ldsm4t(&bf[4], bb + bOff + (unsigned)ks * (16 * ROWB2) + 32);
#pragma unroll
            for (int i = 0; i < 4; i++)
                ldsm4(&af[i * 4], ab + aOff + (unsigned)i * (16 * ROWA) + ks * 32);
#pragma unroll
            for (int i = 0; i < 4; i++)
#pragma unroll
                for (int j = 0; j < 4; j++)
                    mma16816(&acc[(i * 4 + j) * 4], &af[i * 4], &bf[j * 2]);
        }
    }

    float* zsm = (float*)smem;
    int qr = lane >> 2, t4 = lane & 3;
    int n0 = bx * 256, o0 = by * 64;
#pragma unroll
    for (int r = 0; r < 2; r++) {
        __syncthreads();
        if ((wn >> 7) == r) {
            int wnl = wn & 127;
#pragma unroll
            for (int i = 0; i < 4; i++)
#pragma unroll
                for (int j = 0; j < 4; j++) {
                    int m = wm + i * 16 + qr;
                    int n = wnl + j * 8 + t4 * 2;
                    const float* p = &acc[(i * 4 + j) * 4];
                    zsm[n * 132 + m]           = p[0];
                    zsm[(n + 1) * 132 + m]     = p[1];
                    zsm[n * 132 + m + 8]       = p[2];
                    zsm[(n + 1) * 132 + m + 8] = p[3];
                }
        }
        __syncthreads();
#pragma unroll
        for (int it = 0; it < 4; it++) {
            int task = it * 512 + tid;
            int nrow = task >> 4, mg = (task & 15) * 4;
            float4 za = *(const float4*)&zsm[nrow * 132 + mg];
            float4 zg = *(const float4*)&zsm[nrow * 132 + 64 + mg];
            float4 ba = *(const float4*)(bias + o0 + mg);
            float4 bg = *(const float4*)(bias + 1024 + o0 + mg);
            size_t addr = (size_t)(n0 + r * 128 + nrow) * 1024 + o0 + mg;
            float4 hv = *(const float4*)(hs + addr);
            float4 ov;
            ov.x = hv.x + (za.x + ba.x) * (1.0f / (1.0f + expf(-(zg.x + bg.x))));
            ov.y = hv.y + (za.y + ba.y) * (1.0f / (1.0f + expf(-(zg.y + bg.y))));
            ov.z = hv.z + (za.z + ba.z) * (1.0f / (1.0f + expf(-(zg.z + bg.z))));
            ov.w = hv.w + (za.w + ba.w) * (1.0f / (1.0f + expf(-(zg.w + bg.w))));
            *(float4*)(out + addr) = ov;
        }
    }
}

// ---------------- launch ----------------
extern "C" void kernel_launch(void* const* d_in, const int* in_sizes, int n_in,
                              void* d_out, int out_size) {
    const float* hidden     = (const float*)d_in[0];
    const float* attn_mask  = (const float*)d_in[1];
    const float* norm_w     = (const float*)d_in[2];
    const float* log_dt     = (const float*)d_in[3];
    const float* log_A_real = (const float*)d_in[4];
    const float* A_imag     = (const float*)d_in[5];
    const float* C_real     = (const float*)d_in[6];
    const float* C_imag     = (const float*)d_in[7];
    const float* Dvec       = (const float*)d_in[8];
    const float* out_w      = (const float*)d_in[9];
    const float* out_b      = (const float*)d_in[10];
    float* out = (float*)d_out;

    cudaFuncSetAttribute(gemm_glu_kernel, cudaFuncAttributeMaxDynamicSharedMemorySize, GSMEM);
    cudaFuncSetAttribute(norm_fused_kernel, cudaFuncAttributeMaxDynamicSharedMemorySize, NF_SMEM);
    cudaFuncSetAttribute(conv_kernel, cudaFuncAttributeMaxDynamicSharedMemorySize, CONV_SMEM);
    cudaFuncSetAttribute(boundary_kernel, cudaFuncAttributeMaxDynamicSharedMemorySize, BND_SMEM);

    wconv_kernel<<<8192, 256>>>(out_w);
    prep2_kernel<<<Hh, 128>>>(log_dt, log_A_real, A_imag, C_real, C_imag, Dvec);
    norm_fused_kernel<<<dim3(Ll / 32, Bb), 256, NF_SMEM>>>(hidden, attn_mask, norm_w);
    conv_kernel<<<Hh, 512, CONV_SMEM>>>();
    boundary_kernel<<<Hh, 256, BND_SMEM>>>();
    gemm_glu_kernel<<<dim3(16, 64), 512, GSMEM>>>(out_b, hidden, out);
}